// round 1
// baseline (speedup 1.0000x reference)
#include <cuda_runtime.h>
#include <cstdint>
#include <cstddef>

#define N_PTS 32768
#define HID   256
#define KTEST 1024
#define PI_F  3.14159274101257324f

// Scratch: jet buffers [point][channel(3)][256], ping-pong. ~100 MB each.
__device__ float g_bufA[(size_t)N_PTS * 3 * HID];
__device__ float g_bufB[(size_t)N_PTS * 3 * HID];
__device__ float g_r[N_PTS];
__device__ float g_S[KTEST];
__device__ float g_ub[2];

// Flag-independent tanh: (e^{2z}-1)/(e^{2z}+1), |abs err| <~ 3e-7 everywhere.
__device__ __forceinline__ float my_tanh(float z) {
    float zc = fminf(fmaxf(z, -9.0f), 9.0f);
    float e  = __expf(2.0f * zc);
    return (e - 1.0f) / (e + 1.0f);
}

// Accurate sin for |a| <= ~3300 (covers pi*1024*x): Cody-Waite mod pi + odd
// Taylor to x^11.  Deterministic regardless of fast-math flags.
__device__ __forceinline__ float my_sin(float a) {
    const float INV_PI = 0.3183098861837907f;
    float n = rintf(a * INV_PI);
    float r = fmaf(n, -3.14159274101257324f, a);   // a - n*PI_HI (fma-exact)
    r = fmaf(n, 8.742277657347586e-8f, r);         // - n*PI_LO
    float s2 = r * r;
    float p = -2.50521084e-8f;
    p = fmaf(p, s2, 2.75573192e-6f);
    p = fmaf(p, s2, -1.98412698e-4f);
    p = fmaf(p, s2, 8.33333333e-3f);
    p = fmaf(p, s2, -1.66666667e-1f);
    float s = fmaf(p * s2, r, r);
    return (((int)n) & 1) ? -s : s;
}

// Layer 0: z0 = x*W0 + b0; jet init.  h=tanh(z0); d=(1-h^2)W0; e=-2h(1-h^2)W0^2
__global__ void k_init(const float* __restrict__ x, const float* __restrict__ W0,
                       const float* __restrict__ b0, float* __restrict__ out) {
    int i = blockIdx.x, j = threadIdx.x;
    float w  = W0[j];
    float z  = fmaf(x[i], w, b0[j]);
    float h  = my_tanh(z);
    float gg = fmaf(-h, h, 1.0f);
    size_t base = (size_t)i * (3 * HID);
    out[base + j]           = h;
    out[base + HID + j]     = gg * w;
    out[base + 2 * HID + j] = -2.0f * h * gg * w * w;
}

// Hidden layer: fused triple-GEMM [16 pts x 256 cols, K=256] + tanh-jet epilogue.
// Thread tile: 4 points x 4 cols x 3 channels = 48 fp32 accumulators.
__global__ __launch_bounds__(256) void k_layer(const float* __restrict__ in,
                                               float* __restrict__ out,
                                               const float* __restrict__ W,
                                               const float* __restrict__ b) {
    __shared__ float sm[16 * 3 * HID];   // 48 KB: 16 points, 3 channels
    const int tid = threadIdx.x;
    const size_t base = (size_t)blockIdx.x * 16 * 3 * HID;

    // Cooperative load of the 16-point jet tile (contiguous, float4-coalesced)
    const float4* gin = (const float4*)(in + base);
    float4* sm4 = (float4*)sm;
#pragma unroll
    for (int t = 0; t < 12; t++) sm4[tid + t * 256] = gin[tid + t * 256];
    __syncthreads();

    const int tj = tid & 63, tm = tid >> 6;
    const int j0 = tj * 4, m0 = tm * 4;

    float accZ[4][4], accA[4][4], accC[4][4];
#pragma unroll
    for (int mm = 0; mm < 4; mm++)
#pragma unroll
        for (int cc = 0; cc < 4; cc++) {
            accZ[mm][cc] = 0.f; accA[mm][cc] = 0.f; accC[mm][cc] = 0.f;
        }

    for (int k = 0; k < HID; k += 4) {
        float4 w[4];
#pragma unroll
        for (int kk = 0; kk < 4; kk++)
            w[kk] = *(const float4*)(W + (k + kk) * HID + j0);
#pragma unroll
        for (int mm = 0; mm < 4; mm++) {
            const int m = m0 + mm;
            float4 h4 = *(const float4*)(sm + (m * 3 + 0) * HID + k);
            float4 d4 = *(const float4*)(sm + (m * 3 + 1) * HID + k);
            float4 e4 = *(const float4*)(sm + (m * 3 + 2) * HID + k);
            const float hs[4] = {h4.x, h4.y, h4.z, h4.w};
            const float ds[4] = {d4.x, d4.y, d4.z, d4.w};
            const float es[4] = {e4.x, e4.y, e4.z, e4.w};
#pragma unroll
            for (int kk = 0; kk < 4; kk++) {
                const float ws0 = w[kk].x, ws1 = w[kk].y, ws2 = w[kk].z, ws3 = w[kk].w;
                accZ[mm][0] = fmaf(hs[kk], ws0, accZ[mm][0]);
                accZ[mm][1] = fmaf(hs[kk], ws1, accZ[mm][1]);
                accZ[mm][2] = fmaf(hs[kk], ws2, accZ[mm][2]);
                accZ[mm][3] = fmaf(hs[kk], ws3, accZ[mm][3]);
                accA[mm][0] = fmaf(ds[kk], ws0, accA[mm][0]);
                accA[mm][1] = fmaf(ds[kk], ws1, accA[mm][1]);
                accA[mm][2] = fmaf(ds[kk], ws2, accA[mm][2]);
                accA[mm][3] = fmaf(ds[kk], ws3, accA[mm][3]);
                accC[mm][0] = fmaf(es[kk], ws0, accC[mm][0]);
                accC[mm][1] = fmaf(es[kk], ws1, accC[mm][1]);
                accC[mm][2] = fmaf(es[kk], ws2, accC[mm][2]);
                accC[mm][3] = fmaf(es[kk], ws3, accC[mm][3]);
            }
        }
    }

    // Epilogue: tanh jet chain, vectorized stores
    float4 bb = *(const float4*)(b + j0);
    const float bs[4] = {bb.x, bb.y, bb.z, bb.w};
#pragma unroll
    for (int mm = 0; mm < 4; mm++) {
        const int m = m0 + mm;
        float outH[4], outD[4], outE[4];
#pragma unroll
        for (int cc = 0; cc < 4; cc++) {
            float z = accZ[mm][cc] + bs[cc];
            float h = my_tanh(z);
            float g = fmaf(-h, h, 1.0f);
            float a = accA[mm][cc];
            float c = accC[mm][cc];
            outH[cc] = h;
            outD[cc] = g * a;
            outE[cc] = g * fmaf(-2.0f * h * a, a, c);   // g*(c - 2*h*a^2)
        }
        *(float4*)(out + base + (m * 3 + 0) * HID + j0) = *(float4*)outH;
        *(float4*)(out + base + (m * 3 + 1) * HID + j0) = *(float4*)outD;
        *(float4*)(out + base + (m * 3 + 2) * HID + j0) = *(float4*)outE;
    }
}

// Head: u = h2@W3 + b3 (boundary pts only), u_xx = e2@W3; residual r_i.
__global__ void k_head(const float* __restrict__ in, const float* __restrict__ W3,
                       const float* __restrict__ b3, const float* __restrict__ x,
                       const float* __restrict__ wts) {
    int gidx = blockIdx.x * blockDim.x + threadIdx.x;
    int i = gidx >> 5;
    int lane = gidx & 31;
    if (i >= N_PTS) return;
    const float* rowH = in + (size_t)i * (3 * HID);
    const float* rowE = rowH + 2 * HID;
    float su = 0.f, se = 0.f;
#pragma unroll
    for (int j = lane; j < HID; j += 32) {
        float w = W3[j];
        su = fmaf(rowH[j], w, su);
        se = fmaf(rowE[j], w, se);
    }
#pragma unroll
    for (int o = 16; o; o >>= 1) {
        su += __shfl_down_sync(0xffffffffu, su, o);
        se += __shfl_down_sync(0xffffffffu, se, o);
    }
    if (lane == 0) {
        float xi = x[i];
        g_r[i] = wts[i] * (se + my_sin(PI_F * xi));   // w*(u_xx + source)
        if (i == 0)         g_ub[0] = su + b3[0];
        if (i == N_PTS - 1) g_ub[1] = su + b3[0];
    }
}

// Spectral: S_k = sum_i sin(pi*k*x_i) * r_i; 8 k-modes per block so x,r are
// read from L2 only 128x total.
__global__ __launch_bounds__(256) void k_spec(const float* __restrict__ x) {
    const int k0 = blockIdx.x * 8;
    float pk[8];
#pragma unroll
    for (int q = 0; q < 8; q++) pk[q] = PI_F * (float)(k0 + 1 + q);
    float acc[8] = {0, 0, 0, 0, 0, 0, 0, 0};
    for (int i = threadIdx.x; i < N_PTS; i += 256) {
        float xi = x[i], ri = g_r[i];
#pragma unroll
        for (int q = 0; q < 8; q++)
            acc[q] = fmaf(my_sin(pk[q] * xi), ri, acc[q]);
    }
    __shared__ float sred[8][8];
    int lane = threadIdx.x & 31, wid = threadIdx.x >> 5;
#pragma unroll
    for (int q = 0; q < 8; q++) {
        float v = acc[q];
#pragma unroll
        for (int o = 16; o; o >>= 1) v += __shfl_down_sync(0xffffffffu, v, o);
        if (lane == 0) sred[q][wid] = v;
    }
    __syncthreads();
    if (threadIdx.x < 8) {
        float s = 0.f;
#pragma unroll
        for (int w = 0; w < 8; w++) s += sred[threadIdx.x][w];
        g_S[k0 + threadIdx.x] = s;
    }
}

// Final deterministic reduction -> d_out[0]=mean_k S_k^2, d_out[1]=boundary.
__global__ void k_final(float* __restrict__ out) {
    __shared__ float sred[8];
    float s = 0.f;
    for (int t = threadIdx.x; t < KTEST; t += 256) {
        float v = g_S[t];
        s = fmaf(v, v, s);
    }
    int lane = threadIdx.x & 31, wid = threadIdx.x >> 5;
#pragma unroll
    for (int o = 16; o; o >>= 1) s += __shfl_down_sync(0xffffffffu, s, o);
    if (lane == 0) sred[wid] = s;
    __syncthreads();
    if (threadIdx.x == 0) {
        float t = 0.f;
#pragma unroll
        for (int w = 0; w < 8; w++) t += sred[w];
        out[0] = t * (1.0f / 1024.0f);
        out[1] = 5.0f * (g_ub[0] * g_ub[0] + g_ub[1] * g_ub[1]);
    }
}

extern "C" void kernel_launch(void* const* d_in, const int* in_sizes, int n_in,
                              void* d_out, int out_size) {
    const float* x   = (const float*)d_in[0];
    const float* wts = (const float*)d_in[1];
    const float* W0  = (const float*)d_in[2];
    const float* b0  = (const float*)d_in[3];
    const float* W1  = (const float*)d_in[4];
    const float* b1  = (const float*)d_in[5];
    const float* W2  = (const float*)d_in[6];
    const float* b2  = (const float*)d_in[7];
    const float* W3  = (const float*)d_in[8];
    const float* b3  = (const float*)d_in[9];

    void *pA = nullptr, *pB = nullptr;
    cudaGetSymbolAddress(&pA, g_bufA);
    cudaGetSymbolAddress(&pB, g_bufB);
    float* bufA = (float*)pA;
    float* bufB = (float*)pB;

    k_init <<<N_PTS, 256>>>(x, W0, b0, bufA);
    k_layer<<<N_PTS / 16, 256>>>(bufA, bufB, W1, b1);
    k_layer<<<N_PTS / 16, 256>>>(bufB, bufA, W2, b2);
    k_head <<<(N_PTS * 32) / 256, 256>>>(bufA, W3, b3, x, wts);
    k_spec <<<KTEST / 8, 256>>>(x);
    k_final<<<1, 256>>>((float*)d_out);
}

// round 4
// speedup vs baseline: 1.2544x; 1.2544x over previous
#include <cuda_runtime.h>
#include <cuda_bf16.h>
#include <cstdint>
#include <cstddef>

#define N_PTS 32768
#define HID   256
#define KTEST 1024
#define PI_F  3.14159274101257324f

// ---------------- global scratch (fp32 jets, ping-pong) ----------------
__device__ float g_bufA[(size_t)N_PTS * 3 * HID];
__device__ float g_bufB[(size_t)N_PTS * 3 * HID];
__device__ float g_r[N_PTS];
__device__ float g_S[KTEST];
__device__ float g_ub[2];

// ---------------- math helpers (flag-independent) ----------------
__device__ __forceinline__ float my_tanh(float z) {
    float zc = fminf(fmaxf(z, -9.0f), 9.0f);
    float e  = __expf(2.0f * zc);
    return (e - 1.0f) / (e + 1.0f);
}

__device__ __forceinline__ float my_sin(float a) {
    const float INV_PI = 0.3183098861837907f;
    float n = rintf(a * INV_PI);
    float r = fmaf(n, -3.14159274101257324f, a);
    r = fmaf(n, 8.742277657347586e-8f, r);
    float s2 = r * r;
    float p = -2.50521084e-8f;
    p = fmaf(p, s2, 2.75573192e-6f);
    p = fmaf(p, s2, -1.98412698e-4f);
    p = fmaf(p, s2, 8.33333333e-3f);
    p = fmaf(p, s2, -1.66666667e-1f);
    float s = fmaf(p * s2, r, r);
    return (((int)n) & 1) ? -s : s;
}

// bf16 HMMA (sm_80+ PTX — valid on plain sm_103 target, no 'a' features).
__device__ __forceinline__ void mma16816(float* d, const uint32_t* a, const uint32_t* b) {
    asm volatile(
        "mma.sync.aligned.m16n8k16.row.col.f32.bf16.bf16.f32 "
        "{%0,%1,%2,%3}, {%4,%5,%6,%7}, {%8,%9}, {%0,%1,%2,%3};"
        : "+f"(d[0]), "+f"(d[1]), "+f"(d[2]), "+f"(d[3])
        : "r"(a[0]), "r"(a[1]), "r"(a[2]), "r"(a[3]), "r"(b[0]), "r"(b[1]));
}

// ---------------- SMEM geometry (elements of bf16) ----------------
#define SA        72                    // padded K-stride: 144B -> conflict-free
#define A_TILE_E  (128 * SA)            // one (channel, half) A tile
#define B_OFF_E   (6 * A_TILE_E)
#define B_TILE_E  (64 * SA)
#define SMEM_E    (B_OFF_E + 2 * B_TILE_E)
#define SMEM_TOT  (SMEM_E * 2)          // 129024 bytes

// ---------------- kernels ----------------
__global__ void k_init(const float* __restrict__ x, const float* __restrict__ W0,
                       const float* __restrict__ b0, float* __restrict__ out) {
    int i = blockIdx.x, j = threadIdx.x;
    float w  = W0[j];
    float z  = fmaf(x[i], w, b0[j]);
    float h  = my_tanh(z);
    float gg = fmaf(-h, h, 1.0f);
    size_t base = (size_t)i * (3 * HID);
    out[base + j]           = h;
    out[base + HID + j]     = gg * w;
    out[base + 2 * HID + j] = -2.0f * h * gg * w * w;
}

// Hidden layer: split-bf16 (3-pass) triple-GEMM on HMMA + fused tanh-jet epilogue.
// CTA: 128 points x 64 cols; 8 warps in 4x2; warp tile 32x32 x 3 channels.
__global__ __launch_bounds__(256) void k_layer_mma(const float* __restrict__ in,
                                                   float* __restrict__ out,
                                                   const float* __restrict__ W,
                                                   const float* __restrict__ bias) {
    extern __shared__ __nv_bfloat16 sm[];
    const int tid  = threadIdx.x;
    const int wid  = tid >> 5, lane = tid & 31;
    const int wm   = wid & 3,  wn   = wid >> 2;
    const int m0   = (blockIdx.x >> 2) * 128;
    const int n0   = (blockIdx.x & 3) * 64;
    const int lg   = lane >> 2;          // group id (row/col within fragment)
    const int lq   = lane & 3;           // quad id (k within fragment)

    float acc[3][2][4][4];
#pragma unroll
    for (int ch = 0; ch < 3; ch++)
#pragma unroll
        for (int mf = 0; mf < 2; mf++)
#pragma unroll
            for (int nf = 0; nf < 4; nf++)
#pragma unroll
                for (int rr = 0; rr < 4; rr++) acc[ch][mf][nf][rr] = 0.f;

    for (int c = 0; c < 4; c++) {
        const int kc = c * 64;
        __syncthreads();   // previous chunk's compute done before restaging

        // ---- stage A: 3 channels x [128 rows x 64 k] fp32 -> bf16 hi/lo ----
#pragma unroll
        for (int ch = 0; ch < 3; ch++) {
#pragma unroll
            for (int it = 0; it < 8; it++) {
                int e = tid + it * 256;
                int r = e >> 4, c4 = e & 15;
                float4 v = *(const float4*)(in + ((size_t)(m0 + r) * 3 + ch) * HID + kc + c4 * 4);
                float vv[4] = {v.x, v.y, v.z, v.w};
                __nv_bfloat16 hi[4], lo[4];
#pragma unroll
                for (int u = 0; u < 4; u++) {
                    hi[u] = __float2bfloat16(vv[u]);
                    lo[u] = __float2bfloat16(vv[u] - __bfloat162float(hi[u]));
                }
                int off = r * SA + c4 * 4;
                *(uint2*)(sm + (ch * 2 + 0) * A_TILE_E + off) = *(uint2*)hi;
                *(uint2*)(sm + (ch * 2 + 1) * A_TILE_E + off) = *(uint2*)lo;
            }
        }
        // ---- stage B transposed: Bs[n][k] = W[kc+k][n0+n], hi/lo ----
#pragma unroll
        for (int it = 0; it < 4; it++) {
            int e = tid + it * 256;
            int k = e >> 4, n4 = e & 15;
            float4 v = *(const float4*)(W + (size_t)(kc + k) * HID + n0 + n4 * 4);
            float vv[4] = {v.x, v.y, v.z, v.w};
#pragma unroll
            for (int u = 0; u < 4; u++) {
                __nv_bfloat16 hh = __float2bfloat16(vv[u]);
                __nv_bfloat16 ll = __float2bfloat16(vv[u] - __bfloat162float(hh));
                int off = (n4 * 4 + u) * SA + k;
                sm[B_OFF_E + off]            = hh;
                sm[B_OFF_E + B_TILE_E + off] = ll;
            }
        }
        __syncthreads();

        // ---- compute: 4 k-steps of 16 ----
#pragma unroll
        for (int ks = 0; ks < 4; ks++) {
            const int k0 = ks * 16 + lq * 2;
            uint32_t bh[4][2], bl[4][2];
#pragma unroll
            for (int nf = 0; nf < 4; nf++) {
                const __nv_bfloat16* p = sm + B_OFF_E + (wn * 32 + nf * 8 + lg) * SA + k0;
                bh[nf][0] = *(const uint32_t*)p;
                bh[nf][1] = *(const uint32_t*)(p + 8);
                bl[nf][0] = *(const uint32_t*)(p + B_TILE_E);
                bl[nf][1] = *(const uint32_t*)(p + B_TILE_E + 8);
            }
#pragma unroll
            for (int ch = 0; ch < 3; ch++) {
                uint32_t ah[2][4], al[2][4];
#pragma unroll
                for (int mf = 0; mf < 2; mf++) {
                    const __nv_bfloat16* p = sm + (ch * 2) * A_TILE_E
                                           + (wm * 32 + mf * 16 + lg) * SA + k0;
                    ah[mf][0] = *(const uint32_t*)p;
                    ah[mf][1] = *(const uint32_t*)(p + 8 * SA);
                    ah[mf][2] = *(const uint32_t*)(p + 8);
                    ah[mf][3] = *(const uint32_t*)(p + 8 * SA + 8);
                    const __nv_bfloat16* q = p + A_TILE_E;
                    al[mf][0] = *(const uint32_t*)q;
                    al[mf][1] = *(const uint32_t*)(q + 8 * SA);
                    al[mf][2] = *(const uint32_t*)(q + 8);
                    al[mf][3] = *(const uint32_t*)(q + 8 * SA + 8);
                }
#pragma unroll
                for (int mf = 0; mf < 2; mf++)
#pragma unroll
                    for (int nf = 0; nf < 4; nf++) {
                        mma16816(acc[ch][mf][nf], ah[mf], bh[nf]);  // hi*hi
                        mma16816(acc[ch][mf][nf], ah[mf], bl[nf]);  // hi*lo
                        mma16816(acc[ch][mf][nf], al[mf], bh[nf]);  // lo*hi
                    }
            }
        }
    }

    // ---- epilogue: bias + tanh jet, fp32 stores ----
#pragma unroll
    for (int mf = 0; mf < 2; mf++) {
#pragma unroll
        for (int half = 0; half < 2; half++) {
            const int row = m0 + wm * 32 + mf * 16 + lg + half * 8;
#pragma unroll
            for (int nf = 0; nf < 4; nf++) {
                const int col = n0 + wn * 32 + nf * 8 + lq * 2;
                float b0v = __ldg(bias + col), b1v = __ldg(bias + col + 1);
                float z0 = acc[0][mf][nf][half * 2 + 0] + b0v;
                float z1 = acc[0][mf][nf][half * 2 + 1] + b1v;
                float a0 = acc[1][mf][nf][half * 2 + 0];
                float a1 = acc[1][mf][nf][half * 2 + 1];
                float c0 = acc[2][mf][nf][half * 2 + 0];
                float c1 = acc[2][mf][nf][half * 2 + 1];
                float h0 = my_tanh(z0), h1 = my_tanh(z1);
                float g0 = fmaf(-h0, h0, 1.0f), g1 = fmaf(-h1, h1, 1.0f);
                float2 vH = make_float2(h0, h1);
                float2 vD = make_float2(g0 * a0, g1 * a1);
                float2 vE = make_float2(g0 * fmaf(-2.0f * h0 * a0, a0, c0),
                                        g1 * fmaf(-2.0f * h1 * a1, a1, c1));
                size_t base = (size_t)row * 3 * HID + col;
                *(float2*)(out + base)           = vH;
                *(float2*)(out + base + HID)     = vD;
                *(float2*)(out + base + 2 * HID) = vE;
            }
        }
    }
}

__global__ void k_head(const float* __restrict__ in, const float* __restrict__ W3,
                       const float* __restrict__ b3, const float* __restrict__ x,
                       const float* __restrict__ wts) {
    int gidx = blockIdx.x * blockDim.x + threadIdx.x;
    int i = gidx >> 5;
    int lane = gidx & 31;
    if (i >= N_PTS) return;
    const float* rowH = in + (size_t)i * (3 * HID);
    const float* rowE = rowH + 2 * HID;
    float su = 0.f, se = 0.f;
#pragma unroll
    for (int j = lane; j < HID; j += 32) {
        float w = W3[j];
        su = fmaf(rowH[j], w, su);
        se = fmaf(rowE[j], w, se);
    }
#pragma unroll
    for (int o = 16; o; o >>= 1) {
        su += __shfl_down_sync(0xffffffffu, su, o);
        se += __shfl_down_sync(0xffffffffu, se, o);
    }
    if (lane == 0) {
        float xi = x[i];
        g_r[i] = wts[i] * (se + my_sin(PI_F * xi));
        if (i == 0)         g_ub[0] = su + b3[0];
        if (i == N_PTS - 1) g_ub[1] = su + b3[0];
    }
}

__global__ __launch_bounds__(256) void k_spec(const float* __restrict__ x) {
    const int k0 = blockIdx.x * 8;
    float pk[8];
#pragma unroll
    for (int q = 0; q < 8; q++) pk[q] = PI_F * (float)(k0 + 1 + q);
    float acc[8] = {0, 0, 0, 0, 0, 0, 0, 0};
    for (int i = threadIdx.x; i < N_PTS; i += 256) {
        float xi = x[i], ri = g_r[i];
#pragma unroll
        for (int q = 0; q < 8; q++)
            acc[q] = fmaf(my_sin(pk[q] * xi), ri, acc[q]);
    }
    __shared__ float sred[8][8];
    int lane = threadIdx.x & 31, wid = threadIdx.x >> 5;
#pragma unroll
    for (int q = 0; q < 8; q++) {
        float v = acc[q];
#pragma unroll
        for (int o = 16; o; o >>= 1) v += __shfl_down_sync(0xffffffffu, v, o);
        if (lane == 0) sred[q][wid] = v;
    }
    __syncthreads();
    if (threadIdx.x < 8) {
        float s = 0.f;
#pragma unroll
        for (int w = 0; w < 8; w++) s += sred[threadIdx.x][w];
        g_S[k0 + threadIdx.x] = s;
    }
}

__global__ void k_final(float* __restrict__ out) {
    __shared__ float sred[8];
    float s = 0.f;
    for (int t = threadIdx.x; t < KTEST; t += 256) {
        float v = g_S[t];
        s = fmaf(v, v, s);
    }
    int lane = threadIdx.x & 31, wid = threadIdx.x >> 5;
#pragma unroll
    for (int o = 16; o; o >>= 1) s += __shfl_down_sync(0xffffffffu, s, o);
    if (lane == 0) sred[wid] = s;
    __syncthreads();
    if (threadIdx.x == 0) {
        float t = 0.f;
#pragma unroll
        for (int w = 0; w < 8; w++) t += sred[w];
        out[0] = t * (1.0f / 1024.0f);
        out[1] = 5.0f * (g_ub[0] * g_ub[0] + g_ub[1] * g_ub[1]);
    }
}

extern "C" void kernel_launch(void* const* d_in, const int* in_sizes, int n_in,
                              void* d_out, int out_size) {
    const float* x   = (const float*)d_in[0];
    const float* wts = (const float*)d_in[1];
    const float* W0  = (const float*)d_in[2];
    const float* b0  = (const float*)d_in[3];
    const float* W1  = (const float*)d_in[4];
    const float* b1  = (const float*)d_in[5];
    const float* W2  = (const float*)d_in[6];
    const float* b2  = (const float*)d_in[7];
    const float* W3  = (const float*)d_in[8];
    const float* b3  = (const float*)d_in[9];

    void *pA = nullptr, *pB = nullptr;
    cudaGetSymbolAddress(&pA, g_bufA);
    cudaGetSymbolAddress(&pB, g_bufB);
    float* bufA = (float*)pA;
    float* bufB = (float*)pB;

    cudaFuncSetAttribute(k_layer_mma, cudaFuncAttributeMaxDynamicSharedMemorySize, SMEM_TOT);

    k_init     <<<N_PTS, 256>>>(x, W0, b0, bufA);
    k_layer_mma<<<1024, 256, SMEM_TOT>>>(bufA, bufB, W1, b1);
    k_layer_mma<<<1024, 256, SMEM_TOT>>>(bufB, bufA, W2, b2);
    k_head     <<<(N_PTS * 32) / 256, 256>>>(bufA, W3, b3, x, wts);
    k_spec     <<<KTEST / 8, 256>>>(x);
    k_final    <<<1, 256>>>((float*)d_out);
}

// round 5
// speedup vs baseline: 1.3552x; 1.0804x over previous
#include <cuda_runtime.h>
#include <cuda_bf16.h>
#include <cstdint>
#include <cstddef>

#define N_PTS 32768
#define HID   256
#define KTEST 1024
#define PI_F  3.14159274101257324f

// ---------------- global scratch ----------------
// Jet buffer, pre-split bf16: index ((m*3 + ch)*2 + hl)*256 + k
__device__ __nv_bfloat16 g_jet[(size_t)N_PTS * 3 * 2 * HID];
__device__ float g_part[(size_t)N_PTS * 16];   // [row][ch(2)][8 partials]
__device__ float g_r[N_PTS];
__device__ float g_S[KTEST];
__device__ float g_ub[2];

// ---------------- math helpers (flag-independent) ----------------
__device__ __forceinline__ float my_tanh(float z) {
    float zc = fminf(fmaxf(z, -9.0f), 9.0f);
    float e  = __expf(2.0f * zc);
    return (e - 1.0f) / (e + 1.0f);
}

__device__ __forceinline__ float my_sin(float a) {
    const float INV_PI = 0.3183098861837907f;
    float n = rintf(a * INV_PI);
    float r = fmaf(n, -3.14159274101257324f, a);
    r = fmaf(n, 8.742277657347586e-8f, r);
    float s2 = r * r;
    float p = -2.50521084e-8f;
    p = fmaf(p, s2, 2.75573192e-6f);
    p = fmaf(p, s2, -1.98412698e-4f);
    p = fmaf(p, s2, 8.33333333e-3f);
    p = fmaf(p, s2, -1.66666667e-1f);
    float s = fmaf(p * s2, r, r);
    return (((int)n) & 1) ? -s : s;
}

__device__ __forceinline__ void bsplit(float v, __nv_bfloat16& hi, __nv_bfloat16& lo) {
    hi = __float2bfloat16(v);
    lo = __float2bfloat16(v - __bfloat162float(hi));
}

// bf16 HMMA (sm_80+ PTX — valid on plain sm_103 target).
__device__ __forceinline__ void mma16816(float* d, const uint32_t* a, const uint32_t* b) {
    asm volatile(
        "mma.sync.aligned.m16n8k16.row.col.f32.bf16.bf16.f32 "
        "{%0,%1,%2,%3}, {%4,%5,%6,%7}, {%8,%9}, {%0,%1,%2,%3};"
        : "+f"(d[0]), "+f"(d[1]), "+f"(d[2]), "+f"(d[3])
        : "r"(a[0]), "r"(a[1]), "r"(a[2]), "r"(a[3]), "r"(b[0]), "r"(b[1]));
}

__device__ __forceinline__ uint32_t smem_u32(const void* p) {
    uint32_t a;
    asm("{ .reg .u64 t; cvta.to.shared.u64 t, %1; cvt.u32.u64 %0, t; }" : "=r"(a) : "l"(p));
    return a;
}

// ---------------- SMEM geometry (bf16 elements) ----------------
#define SB_E    264                  // B k-stride (256 + 8 pad) -> conflict-free
#define BHI_E   0
#define BLO_E   16896                // 64 * 264
#define AB_E    33792                // A region start
#define SA1     72                   // layer-1 A stride (K=64 chunk)
#define SA2     40                   // layer-2 A stride (K=32 chunk)
#define TILE1_E (128 * SA1)          // 9216
#define TILE2_E (128 * SA2)          // 5120
#define ABUF_E  (6 * TILE2_E)        // 30720 (one cp.async buffer)
#define SMEM1   ((AB_E + 6 * TILE1_E) * 2)    // 178176 B
#define SMEM2   ((AB_E + 12 * TILE2_E) * 2)   // 190464 B

// ---------------- compute core (shared by both layers) ----------------
template<int KS, int ASTRIDE, int TILE>
__device__ __forceinline__ void compute_chunk(
    const __nv_bfloat16* sm, int aBase, int bK0,
    int wm, int wn, int lg, int lq, float (*acc)[2][4][4])
{
#pragma unroll
    for (int ks = 0; ks < KS; ks++) {
        const int ka = ks * 16 + lq * 2;
        const int kb = bK0 + ka;
        uint32_t bh[4][2], bl[4][2];
#pragma unroll
        for (int nf = 0; nf < 4; nf++) {
            const __nv_bfloat16* p = sm + (wn * 32 + nf * 8 + lg) * SB_E + kb;
            bh[nf][0] = *(const uint32_t*)p;
            bh[nf][1] = *(const uint32_t*)(p + 8);
            bl[nf][0] = *(const uint32_t*)(p + BLO_E);
            bl[nf][1] = *(const uint32_t*)(p + BLO_E + 8);
        }
#pragma unroll
        for (int ch = 0; ch < 3; ch++) {
            uint32_t ah[2][4], al[2][4];
#pragma unroll
            for (int mf = 0; mf < 2; mf++) {
                const __nv_bfloat16* p = sm + aBase + (ch * 2) * TILE
                                       + (wm * 32 + mf * 16 + lg) * ASTRIDE + ka;
                ah[mf][0] = *(const uint32_t*)p;
                ah[mf][1] = *(const uint32_t*)(p + 8 * ASTRIDE);
                ah[mf][2] = *(const uint32_t*)(p + 8);
                ah[mf][3] = *(const uint32_t*)(p + 8 * ASTRIDE + 8);
                const __nv_bfloat16* q = p + TILE;
                al[mf][0] = *(const uint32_t*)q;
                al[mf][1] = *(const uint32_t*)(q + 8 * ASTRIDE);
                al[mf][2] = *(const uint32_t*)(q + 8);
                al[mf][3] = *(const uint32_t*)(q + 8 * ASTRIDE + 8);
            }
#pragma unroll
            for (int mf = 0; mf < 2; mf++)
#pragma unroll
                for (int nf = 0; nf < 4; nf++) {
                    mma16816(acc[ch * 2 * 4 / 8 + 0][0][0], nullptr, nullptr); // placeholder never used
                }
            // (real MMA issue below; placeholder removed by specialization)
        }
    }
}

// NOTE: the template above can't express acc[ch] cleanly with the pointer type;
// use a macro-free explicit version instead:
template<int KS, int ASTRIDE, int TILE>
__device__ __forceinline__ void compute_chunk2(
    const __nv_bfloat16* sm, int aBase, int bK0,
    int wm, int wn, int lg, int lq, float acc[3][2][4][4])
{
#pragma unroll
    for (int ks = 0; ks < KS; ks++) {
        const int ka = ks * 16 + lq * 2;
        const int kb = bK0 + ka;
        uint32_t bh[4][2], bl[4][2];
#pragma unroll
        for (int nf = 0; nf < 4; nf++) {
            const __nv_bfloat16* p = sm + (wn * 32 + nf * 8 + lg) * SB_E + kb;
            bh[nf][0] = *(const uint32_t*)p;
            bh[nf][1] = *(const uint32_t*)(p + 8);
            bl[nf][0] = *(const uint32_t*)(p + BLO_E);
            bl[nf][1] = *(const uint32_t*)(p + BLO_E + 8);
        }
#pragma unroll
        for (int ch = 0; ch < 3; ch++) {
            uint32_t ah[2][4], al[2][4];
#pragma unroll
            for (int mf = 0; mf < 2; mf++) {
                const __nv_bfloat16* p = sm + aBase + (ch * 2) * TILE
                                       + (wm * 32 + mf * 16 + lg) * ASTRIDE + ka;
                ah[mf][0] = *(const uint32_t*)p;
                ah[mf][1] = *(const uint32_t*)(p + 8 * ASTRIDE);
                ah[mf][2] = *(const uint32_t*)(p + 8);
                ah[mf][3] = *(const uint32_t*)(p + 8 * ASTRIDE + 8);
                const __nv_bfloat16* q = p + TILE;
                al[mf][0] = *(const uint32_t*)q;
                al[mf][1] = *(const uint32_t*)(q + 8 * ASTRIDE);
                al[mf][2] = *(const uint32_t*)(q + 8);
                al[mf][3] = *(const uint32_t*)(q + 8 * ASTRIDE + 8);
            }
#pragma unroll
            for (int mf = 0; mf < 2; mf++)
#pragma unroll
                for (int nf = 0; nf < 4; nf++) {
                    mma16816(acc[ch][mf][nf], ah[mf], bh[nf]);  // hi*hi
                    mma16816(acc[ch][mf][nf], ah[mf], bl[nf]);  // hi*lo
                    mma16816(acc[ch][mf][nf], al[mf], bh[nf]);  // lo*hi
                }
        }
    }
}

// cp.async prefetch of one K=32 A-chunk from g_jet (layer 2 only).
__device__ __forceinline__ void issue_chunk(uint32_t smA_byte, int m0, int c, int tid) {
    const int kc = c * 32;
    const uint32_t dbase = smA_byte + (uint32_t)((c & 1) * ABUF_E) * 2;
#pragma unroll
    for (int it = 0; it < 12; it++) {
        int seg = tid + it * 256;
        int t = seg >> 9, rem = seg & 511;
        int r = rem >> 2, s4 = rem & 3;
        const __nv_bfloat16* src = g_jet
            + (((size_t)((m0 + r) * 3 + (t >> 1)) * 2 + (t & 1)) << 8) + kc + s4 * 8;
        uint32_t dst = dbase + (uint32_t)(t * TILE2_E + r * SA2 + s4 * 8) * 2;
        unsigned long long gsrc = (unsigned long long)__cvta_generic_to_global(src);
        asm volatile("cp.async.cg.shared.global [%0], [%1], 16;" :: "r"(dst), "l"(gsrc) : "memory");
    }
    asm volatile("cp.async.commit_group;" ::: "memory");
}

// ---------------- fused layer kernel ----------------
// FIRST=1: A computed on-the-fly from (x, W0, b0); writes split-bf16 jets.
// FIRST=0: A via cp.async from g_jet; writes head partial dots to g_part.
template<int FIRST>
__global__ __launch_bounds__(256) void k_layer(
    const float* __restrict__ x, const float* __restrict__ W0v,
    const float* __restrict__ b0v, const float* __restrict__ W,
    const float* __restrict__ bias, const float* __restrict__ W3)
{
    extern __shared__ __nv_bfloat16 sm[];
    const int tid = threadIdx.x, lane = tid & 31, wid = tid >> 5;
    const int wm = wid & 3, wn = wid >> 2;
    const int lg = lane >> 2, lq = lane & 3;
    const int nt = blockIdx.x & 3, mt = blockIdx.x >> 2;
    const int m0 = mt * 128, n0 = nt * 64;

    // ---- stage B (full K=256): W[k][n] -> Bhi/Blo [n][k] ----
#pragma unroll
    for (int it = 0; it < 16; it++) {
        int e = tid + it * 256;
        int k = e >> 4, n4 = e & 15;
        float4 v = *(const float4*)(W + (size_t)k * HID + n0 + n4 * 4);
        float vv[4] = {v.x, v.y, v.z, v.w};
#pragma unroll
        for (int u = 0; u < 4; u++) {
            __nv_bfloat16 hh, ll; bsplit(vv[u], hh, ll);
            int off = (n4 * 4 + u) * SB_E + k;
            sm[BHI_E + off] = hh;
            sm[BLO_E + off] = ll;
        }
    }

    float acc[3][2][4][4];
#pragma unroll
    for (int ch = 0; ch < 3; ch++)
#pragma unroll
        for (int mf = 0; mf < 2; mf++)
#pragma unroll
            for (int nf = 0; nf < 4; nf++)
#pragma unroll
                for (int rr = 0; rr < 4; rr++) acc[ch][mf][nf][rr] = 0.f;

    if (FIRST) {
        // ---- 4 chunks of K=64, A computed analytically ----
        const int m = tid >> 1, k0 = (tid & 1) * 32;
        const float xm = __ldg(x + m0 + m);
        for (int c = 0; c < 4; c++) {
            const int kc = c * 64;
            __syncthreads();   // prev compute done (covers B staging at c=0)
#pragma unroll
            for (int kb = 0; kb < 4; kb++) {
                uint4 sbuf[6];
                __nv_bfloat16* hb = (__nv_bfloat16*)sbuf;
#pragma unroll
                for (int kk = 0; kk < 8; kk++) {
                    int k = kc + k0 + kb * 8 + kk;
                    float w = __ldg(W0v + k), b = __ldg(b0v + k);
                    float z = fmaf(xm, w, b);
                    float h = my_tanh(z);
                    float g = fmaf(-h, h, 1.0f);
                    float d = g * w;
                    float e2 = -2.0f * h * g * w * w;
                    bsplit(h,  hb[0 * 8 + kk], hb[1 * 8 + kk]);
                    bsplit(d,  hb[2 * 8 + kk], hb[3 * 8 + kk]);
                    bsplit(e2, hb[4 * 8 + kk], hb[5 * 8 + kk]);
                }
#pragma unroll
                for (int t = 0; t < 6; t++)
                    *(uint4*)(sm + AB_E + t * TILE1_E + m * SA1 + k0 + kb * 8) = sbuf[t];
            }
            __syncthreads();
            compute_chunk2<4, SA1, TILE1_E>(sm, AB_E, kc, wm, wn, lg, lq, acc);
        }
    } else {
        // ---- 8 chunks of K=32, cp.async double-buffered ----
        const uint32_t smA = smem_u32(sm) + AB_E * 2;
        issue_chunk(smA, m0, 0, tid);
        issue_chunk(smA, m0, 1, tid);
        for (int c = 0; c < 8; c++) {
            if (c < 7) { asm volatile("cp.async.wait_group 1;" ::: "memory"); }
            else       { asm volatile("cp.async.wait_group 0;" ::: "memory"); }
            __syncthreads();
            compute_chunk2<2, SA2, TILE2_E>(sm, AB_E + (c & 1) * ABUF_E, c * 32,
                                            wm, wn, lg, lq, acc);
            __syncthreads();
            if (c + 2 < 8) issue_chunk(smA, m0, c + 2, tid);
        }
    }

    // ---- epilogue ----
    if (FIRST) {
#pragma unroll
        for (int mf = 0; mf < 2; mf++)
#pragma unroll
            for (int rh = 0; rh < 2; rh++) {
                const int row = m0 + wm * 32 + mf * 16 + rh * 8 + lg;
#pragma unroll
                for (int nf = 0; nf < 4; nf++) {
                    const int col = n0 + wn * 32 + nf * 8 + lq * 2;
                    float z0 = acc[0][mf][nf][rh * 2 + 0] + __ldg(bias + col);
                    float z1 = acc[0][mf][nf][rh * 2 + 1] + __ldg(bias + col + 1);
                    float a0 = acc[1][mf][nf][rh * 2 + 0], a1 = acc[1][mf][nf][rh * 2 + 1];
                    float c0 = acc[2][mf][nf][rh * 2 + 0], c1 = acc[2][mf][nf][rh * 2 + 1];
                    float h0 = my_tanh(z0), h1 = my_tanh(z1);
                    float g0 = fmaf(-h0, h0, 1.0f), g1 = fmaf(-h1, h1, 1.0f);
                    float d0 = g0 * a0, d1 = g1 * a1;
                    float e0 = g0 * fmaf(-2.0f * h0 * a0, a0, c0);
                    float e1 = g1 * fmaf(-2.0f * h1 * a1, a1, c1);
                    float vs[3][2] = {{h0, h1}, {d0, d1}, {e0, e1}};
#pragma unroll
                    for (int ch = 0; ch < 3; ch++) {
                        __nv_bfloat16 hA, lA, hB, lB;
                        bsplit(vs[ch][0], hA, lA);
                        bsplit(vs[ch][1], hB, lB);
                        __nv_bfloat162 hp = __halves2bfloat162(hA, hB);
                        __nv_bfloat162 lp = __halves2bfloat162(lA, lB);
                        *(uint32_t*)(g_jet + ((size_t)(row * 3 + ch) * 2 + 0) * HID + col) = *(uint32_t*)&hp;
                        *(uint32_t*)(g_jet + ((size_t)(row * 3 + ch) * 2 + 1) * HID + col) = *(uint32_t*)&lp;
                    }
                }
            }
    } else {
        float su[2][2] = {{0.f, 0.f}, {0.f, 0.f}};
        float se[2][2] = {{0.f, 0.f}, {0.f, 0.f}};
#pragma unroll
        for (int mf = 0; mf < 2; mf++)
#pragma unroll
            for (int rh = 0; rh < 2; rh++)
#pragma unroll
                for (int nf = 0; nf < 4; nf++) {
                    const int col = n0 + wn * 32 + nf * 8 + lq * 2;
                    float z0 = acc[0][mf][nf][rh * 2 + 0] + __ldg(bias + col);
                    float z1 = acc[0][mf][nf][rh * 2 + 1] + __ldg(bias + col + 1);
                    float a0 = acc[1][mf][nf][rh * 2 + 0], a1 = acc[1][mf][nf][rh * 2 + 1];
                    float c0 = acc[2][mf][nf][rh * 2 + 0], c1 = acc[2][mf][nf][rh * 2 + 1];
                    float h0 = my_tanh(z0), h1 = my_tanh(z1);
                    float g0 = fmaf(-h0, h0, 1.0f), g1 = fmaf(-h1, h1, 1.0f);
                    float e0 = g0 * fmaf(-2.0f * h0 * a0, a0, c0);
                    float e1 = g1 * fmaf(-2.0f * h1 * a1, a1, c1);
                    float w30 = __ldg(W3 + col), w31 = __ldg(W3 + col + 1);
                    su[mf][rh] = fmaf(h0, w30, fmaf(h1, w31, su[mf][rh]));
                    se[mf][rh] = fmaf(e0, w30, fmaf(e1, w31, se[mf][rh]));
                }
#pragma unroll
        for (int mf = 0; mf < 2; mf++)
#pragma unroll
            for (int rh = 0; rh < 2; rh++) {
                float s = su[mf][rh];
                s += __shfl_xor_sync(0xffffffffu, s, 1);
                s += __shfl_xor_sync(0xffffffffu, s, 2);
                float t = se[mf][rh];
                t += __shfl_xor_sync(0xffffffffu, t, 1);
                t += __shfl_xor_sync(0xffffffffu, t, 2);
                if (lq == 0) {
                    const int row = m0 + wm * 32 + mf * 16 + rh * 8 + lg;
                    const int p = nt * 2 + wn;
                    g_part[(size_t)row * 16 + p]     = s;
                    g_part[(size_t)row * 16 + 8 + p] = t;
                }
            }
    }
}

// ---------------- tiny kernels ----------------
__global__ void k_head(const float* __restrict__ x, const float* __restrict__ wts,
                       const float* __restrict__ b3) {
    int i = blockIdx.x * 256 + threadIdx.x;
    const float* p = g_part + (size_t)i * 16;
    float4 a0 = *(const float4*)p,       a1 = *(const float4*)(p + 4);
    float4 a2 = *(const float4*)(p + 8), a3 = *(const float4*)(p + 12);
    float su = ((a0.x + a0.y) + (a0.z + a0.w)) + ((a1.x + a1.y) + (a1.z + a1.w));
    float se = ((a2.x + a2.y) + (a2.z + a2.w)) + ((a3.x + a3.y) + (a3.z + a3.w));
    float xi = x[i];
    g_r[i] = wts[i] * (se + my_sin(PI_F * xi));
    if (i == 0)         g_ub[0] = su + __ldg(b3);
    if (i == N_PTS - 1) g_ub[1] = su + __ldg(b3);
}

__global__ __launch_bounds__(256) void k_spec(const float* __restrict__ x) {
    const int k0 = blockIdx.x * 8;
    float pk[8];
#pragma unroll
    for (int q = 0; q < 8; q++) pk[q] = PI_F * (float)(k0 + 1 + q);
    float acc[8] = {0, 0, 0, 0, 0, 0, 0, 0};
    for (int i = threadIdx.x; i < N_PTS; i += 256) {
        float xi = x[i], ri = g_r[i];
#pragma unroll
        for (int q = 0; q < 8; q++)
            acc[q] = fmaf(my_sin(pk[q] * xi), ri, acc[q]);
    }
    __shared__ float sred[8][8];
    int lane = threadIdx.x & 31, wid = threadIdx.x >> 5;
#pragma unroll
    for (int q = 0; q < 8; q++) {
        float v = acc[q];
#pragma unroll
        for (int o = 16; o; o >>= 1) v += __shfl_down_sync(0xffffffffu, v, o);
        if (lane == 0) sred[q][wid] = v;
    }
    __syncthreads();
    if (threadIdx.x < 8) {
        float s = 0.f;
#pragma unroll
        for (int w = 0; w < 8; w++) s += sred[threadIdx.x][w];
        g_S[k0 + threadIdx.x] = s;
    }
}

__global__ void k_final(float* __restrict__ out) {
    __shared__ float sred[8];
    float s = 0.f;
    for (int t = threadIdx.x; t < KTEST; t += 256) {
        float v = g_S[t];
        s = fmaf(v, v, s);
    }
    int lane = threadIdx.x & 31, wid = threadIdx.x >> 5;
#pragma unroll
    for (int o = 16; o; o >>= 1) s += __shfl_down_sync(0xffffffffu, s, o);
    if (lane == 0) sred[wid] = s;
    __syncthreads();
    if (threadIdx.x == 0) {
        float t = 0.f;
#pragma unroll
        for (int w = 0; w < 8; w++) t += sred[w];
        out[0] = t * (1.0f / 1024.0f);
        out[1] = 5.0f * (g_ub[0] * g_ub[0] + g_ub[1] * g_ub[1]);
    }
}

extern "C" void kernel_launch(void* const* d_in, const int* in_sizes, int n_in,
                              void* d_out, int out_size) {
    const float* x   = (const float*)d_in[0];
    const float* wts = (const float*)d_in[1];
    const float* W0  = (const float*)d_in[2];
    const float* b0  = (const float*)d_in[3];
    const float* W1  = (const float*)d_in[4];
    const float* b1  = (const float*)d_in[5];
    const float* W2  = (const float*)d_in[6];
    const float* b2  = (const float*)d_in[7];
    const float* W3  = (const float*)d_in[8];
    const float* b3  = (const float*)d_in[9];

    cudaFuncSetAttribute(k_layer<1>, cudaFuncAttributeMaxDynamicSharedMemorySize, SMEM1);
    cudaFuncSetAttribute(k_layer<0>, cudaFuncAttributeMaxDynamicSharedMemorySize, SMEM2);

    k_layer<1><<<1024, 256, SMEM1>>>(x, W0, b0, W1, b1, nullptr);
    k_layer<0><<<1024, 256, SMEM2>>>(x, W0, b0, W2, b2, W3);
    k_head <<<N_PTS / 256, 256>>>(x, wts, b3);
    k_spec <<<KTEST / 8, 256>>>(x);
    k_final<<<1, 256>>>((float*)d_out);
}

// round 6
// speedup vs baseline: 1.7764x; 1.3107x over previous
#include <cuda_runtime.h>
#include <cuda_bf16.h>
#include <cstdint>
#include <cstddef>

#define N_PTS 32768
#define HID   256
#define KTEST 1024
#define PI_F  3.14159274101257324f

// ---------------- global scratch ----------------
// Jet buffers, pre-split bf16: index ((m*3 + ch)*2 + hl)*256 + k
__device__ __nv_bfloat16 g_jetA[(size_t)N_PTS * 3 * 2 * HID];
__device__ __nv_bfloat16 g_jetB[(size_t)N_PTS * 3 * 2 * HID];
__device__ float g_part[(size_t)N_PTS * 16];   // [row][ch(2)][8 partials]
__device__ float g_r[N_PTS];
__device__ float g_Sp[8 * KTEST];              // [seg][k] spectral partials
__device__ float g_ub[2];

// ---------------- math helpers (flag-independent) ----------------
__device__ __forceinline__ float my_tanh(float z) {
    float zc = fminf(fmaxf(z, -9.0f), 9.0f);
    float e  = __expf(2.0f * zc);
    return __fdividef(e - 1.0f, e + 1.0f);
}

__device__ __forceinline__ float my_sin(float a) {
    const float INV_PI = 0.3183098861837907f;
    float n = rintf(a * INV_PI);
    float r = fmaf(n, -3.14159274101257324f, a);
    r = fmaf(n, 8.742277657347586e-8f, r);
    float s2 = r * r;
    float p = -2.50521084e-8f;
    p = fmaf(p, s2, 2.75573192e-6f);
    p = fmaf(p, s2, -1.98412698e-4f);
    p = fmaf(p, s2, 8.33333333e-3f);
    p = fmaf(p, s2, -1.66666667e-1f);
    float s = fmaf(p * s2, r, r);
    return (((int)n) & 1) ? -s : s;
}

__device__ __forceinline__ void bsplit(float v, __nv_bfloat16& hi, __nv_bfloat16& lo) {
    hi = __float2bfloat16(v);
    lo = __float2bfloat16(v - __bfloat162float(hi));
}

// bf16 HMMA (sm_80+ PTX — valid on plain sm_103 target).
__device__ __forceinline__ void mma16816(float* d, const uint32_t* a, const uint32_t* b) {
    asm volatile(
        "mma.sync.aligned.m16n8k16.row.col.f32.bf16.bf16.f32 "
        "{%0,%1,%2,%3}, {%4,%5,%6,%7}, {%8,%9}, {%0,%1,%2,%3};"
        : "+f"(d[0]), "+f"(d[1]), "+f"(d[2]), "+f"(d[3])
        : "r"(a[0]), "r"(a[1]), "r"(a[2]), "r"(a[3]), "r"(b[0]), "r"(b[1]));
}

__device__ __forceinline__ uint32_t smem_u32(const void* p) {
    uint32_t a;
    asm("{ .reg .u64 t; cvta.to.shared.u64 t, %1; cvt.u32.u64 %0, t; }" : "=r"(a) : "l"(p));
    return a;
}

// ---------------- SMEM geometry (bf16 elements) ----------------
#define SB_E    264                  // B k-stride (256 + 8 pad) -> conflict-free
#define BHI_E   0
#define BLO_E   16896                // 64 * 264
#define AB_E    33792                // A region start
#define SA2     40                   // A k-stride (K=32 chunk + pad)
#define TILE2_E (128 * SA2)          // 5120
#define ABUF_E  (6 * TILE2_E)        // 30720 (one double-buffer half)
#define SMEM2   ((AB_E + 12 * TILE2_E) * 2)   // 190464 B

// ---------------- MMA compute for one K=32 chunk ----------------
__device__ __forceinline__ void compute_chunk(
    const __nv_bfloat16* sm, int aBase, int bK0,
    int wm, int wn, int lg, int lq, float acc[3][2][4][4])
{
#pragma unroll
    for (int ks = 0; ks < 2; ks++) {
        const int ka = ks * 16 + lq * 2;
        const int kb = bK0 + ka;
        uint32_t bh[4][2], bl[4][2];
#pragma unroll
        for (int nf = 0; nf < 4; nf++) {
            const __nv_bfloat16* p = sm + (wn * 32 + nf * 8 + lg) * SB_E + kb;
            bh[nf][0] = *(const uint32_t*)p;
            bh[nf][1] = *(const uint32_t*)(p + 8);
            bl[nf][0] = *(const uint32_t*)(p + BLO_E);
            bl[nf][1] = *(const uint32_t*)(p + BLO_E + 8);
        }
#pragma unroll
        for (int ch = 0; ch < 3; ch++) {
            uint32_t ah[2][4], al[2][4];
#pragma unroll
            for (int mf = 0; mf < 2; mf++) {
                const __nv_bfloat16* p = sm + aBase + (ch * 2) * TILE2_E
                                       + (wm * 32 + mf * 16 + lg) * SA2 + ka;
                ah[mf][0] = *(const uint32_t*)p;
                ah[mf][1] = *(const uint32_t*)(p + 8 * SA2);
                ah[mf][2] = *(const uint32_t*)(p + 8);
                ah[mf][3] = *(const uint32_t*)(p + 8 * SA2 + 8);
                const __nv_bfloat16* q = p + TILE2_E;
                al[mf][0] = *(const uint32_t*)q;
                al[mf][1] = *(const uint32_t*)(q + 8 * SA2);
                al[mf][2] = *(const uint32_t*)(q + 8);
                al[mf][3] = *(const uint32_t*)(q + 8 * SA2 + 8);
            }
#pragma unroll
            for (int mf = 0; mf < 2; mf++)
#pragma unroll
                for (int nf = 0; nf < 4; nf++) {
                    mma16816(acc[ch][mf][nf], ah[mf], bh[nf]);  // hi*hi
                    mma16816(acc[ch][mf][nf], ah[mf], bl[nf]);  // hi*lo
                    mma16816(acc[ch][mf][nf], al[mf], bh[nf]);  // lo*hi
                }
        }
    }
}

// cp.async prefetch of one K=32 A-chunk from a jet buffer.
__device__ __forceinline__ void issue_chunk(uint32_t smA_byte, const __nv_bfloat16* jin,
                                            int m0, int c, int tid) {
    const int kc = c * 32;
    const uint32_t dbase = smA_byte + (uint32_t)((c & 1) * ABUF_E) * 2;
#pragma unroll
    for (int it = 0; it < 12; it++) {
        int seg = tid + it * 256;
        int t = seg >> 9, rem = seg & 511;
        int r = rem >> 2, s4 = rem & 3;
        const __nv_bfloat16* src = jin
            + (((size_t)((m0 + r) * 3 + (t >> 1)) * 2 + (t & 1)) << 8) + kc + s4 * 8;
        uint32_t dst = dbase + (uint32_t)(t * TILE2_E + r * SA2 + s4 * 8) * 2;
        unsigned long long gsrc = (unsigned long long)__cvta_generic_to_global(src);
        asm volatile("cp.async.cg.shared.global [%0], [%1], 16;" :: "r"(dst), "l"(gsrc) : "memory");
    }
    asm volatile("cp.async.commit_group;" ::: "memory");
}

// ---------------- layer-0 jet init (split bf16) ----------------
__global__ __launch_bounds__(256) void k_init(const float* __restrict__ x,
                                              const float* __restrict__ W0,
                                              const float* __restrict__ b0) {
    int gid = blockIdx.x * 256 + threadIdx.x;
    int m  = gid >> 7;
    int k  = (gid & 127) * 2;
    float xm = __ldg(x + m);
    __nv_bfloat162 st[6];
    __nv_bfloat16* hb = (__nv_bfloat16*)st;
#pragma unroll
    for (int u = 0; u < 2; u++) {
        float w = __ldg(W0 + k + u), b = __ldg(b0 + k + u);
        float z = fmaf(xm, w, b);
        float h = my_tanh(z);
        float g = fmaf(-h, h, 1.0f);
        float d = g * w;
        float e2 = -2.0f * h * g * w * w;
        bsplit(h,  hb[0 * 2 + u], hb[1 * 2 + u]);
        bsplit(d,  hb[2 * 2 + u], hb[3 * 2 + u]);
        bsplit(e2, hb[4 * 2 + u], hb[5 * 2 + u]);
    }
#pragma unroll
    for (int ch = 0; ch < 3; ch++) {
#pragma unroll
        for (int hl = 0; hl < 2; hl++) {
            *(uint32_t*)(g_jetA + (((size_t)(m * 3 + ch) * 2 + hl) << 8) + k)
                = *(uint32_t*)&st[ch * 2 + hl];
        }
    }
}

// ---------------- fused hidden layer ----------------
// WRITE_JET=1: epilogue writes split-bf16 jets to jout (layer 1).
// WRITE_JET=0: epilogue writes head partial dots to g_part (layer 2).
template<int WRITE_JET>
__global__ __launch_bounds__(256) void k_layer(
    const __nv_bfloat16* __restrict__ jin, __nv_bfloat16* __restrict__ jout,
    const float* __restrict__ W, const float* __restrict__ bias,
    const float* __restrict__ W3)
{
    extern __shared__ __nv_bfloat16 sm[];
    const int tid = threadIdx.x, lane = tid & 31, wid = tid >> 5;
    const int wm = wid & 3, wn = wid >> 2;
    const int lg = lane >> 2, lq = lane & 3;
    const int nt = blockIdx.x & 3, mt = blockIdx.x >> 2;
    const int m0 = mt * 128, n0 = nt * 64;

    const uint32_t smA = smem_u32(sm) + AB_E * 2;
    issue_chunk(smA, jin, m0, 0, tid);
    issue_chunk(smA, jin, m0, 1, tid);

    // ---- stage B (full K=256): W[k][n] -> Bhi/Blo [n][k] ----
#pragma unroll
    for (int it = 0; it < 16; it++) {
        int e = tid + it * 256;
        int k = e >> 4, n4 = e & 15;
        float4 v = *(const float4*)(W + (size_t)k * HID + n0 + n4 * 4);
        float vv[4] = {v.x, v.y, v.z, v.w};
#pragma unroll
        for (int u = 0; u < 4; u++) {
            __nv_bfloat16 hh, ll; bsplit(vv[u], hh, ll);
            int off = (n4 * 4 + u) * SB_E + k;
            sm[BHI_E + off] = hh;
            sm[BLO_E + off] = ll;
        }
    }

    float acc[3][2][4][4];
#pragma unroll
    for (int ch = 0; ch < 3; ch++)
#pragma unroll
        for (int mf = 0; mf < 2; mf++)
#pragma unroll
            for (int nf = 0; nf < 4; nf++)
#pragma unroll
                for (int rr = 0; rr < 4; rr++) acc[ch][mf][nf][rr] = 0.f;

    // ---- 8 chunks of K=32, cp.async double-buffered ----
    for (int c = 0; c < 8; c++) {
        if (c < 7) { asm volatile("cp.async.wait_group 1;" ::: "memory"); }
        else       { asm volatile("cp.async.wait_group 0;" ::: "memory"); }
        __syncthreads();
        compute_chunk(sm, AB_E + (c & 1) * ABUF_E, c * 32, wm, wn, lg, lq, acc);
        __syncthreads();
        if (c + 2 < 8) issue_chunk(smA, jin, m0, c + 2, tid);
    }

    // ---- epilogue ----
    if (WRITE_JET) {
#pragma unroll
        for (int mf = 0; mf < 2; mf++)
#pragma unroll
            for (int rh = 0; rh < 2; rh++) {
                const int row = m0 + wm * 32 + mf * 16 + rh * 8 + lg;
#pragma unroll
                for (int nf = 0; nf < 4; nf++) {
                    const int col = n0 + wn * 32 + nf * 8 + lq * 2;
                    float z0 = acc[0][mf][nf][rh * 2 + 0] + __ldg(bias + col);
                    float z1 = acc[0][mf][nf][rh * 2 + 1] + __ldg(bias + col + 1);
                    float a0 = acc[1][mf][nf][rh * 2 + 0], a1 = acc[1][mf][nf][rh * 2 + 1];
                    float c0 = acc[2][mf][nf][rh * 2 + 0], c1 = acc[2][mf][nf][rh * 2 + 1];
                    float h0 = my_tanh(z0), h1 = my_tanh(z1);
                    float g0 = fmaf(-h0, h0, 1.0f), g1 = fmaf(-h1, h1, 1.0f);
                    float d0 = g0 * a0, d1 = g1 * a1;
                    float e0 = g0 * fmaf(-2.0f * h0 * a0, a0, c0);
                    float e1 = g1 * fmaf(-2.0f * h1 * a1, a1, c1);
                    float vs[3][2] = {{h0, h1}, {d0, d1}, {e0, e1}};
#pragma unroll
                    for (int ch = 0; ch < 3; ch++) {
                        __nv_bfloat16 hA, lA, hB, lB;
                        bsplit(vs[ch][0], hA, lA);
                        bsplit(vs[ch][1], hB, lB);
                        __nv_bfloat162 hp = __halves2bfloat162(hA, hB);
                        __nv_bfloat162 lp = __halves2bfloat162(lA, lB);
                        *(uint32_t*)(jout + (((size_t)(row * 3 + ch) * 2 + 0) << 8) + col) = *(uint32_t*)&hp;
                        *(uint32_t*)(jout + (((size_t)(row * 3 + ch) * 2 + 1) << 8) + col) = *(uint32_t*)&lp;
                    }
                }
            }
    } else {
        float su[2][2] = {{0.f, 0.f}, {0.f, 0.f}};
        float se[2][2] = {{0.f, 0.f}, {0.f, 0.f}};
#pragma unroll
        for (int mf = 0; mf < 2; mf++)
#pragma unroll
            for (int rh = 0; rh < 2; rh++)
#pragma unroll
                for (int nf = 0; nf < 4; nf++) {
                    const int col = n0 + wn * 32 + nf * 8 + lq * 2;
                    float z0 = acc[0][mf][nf][rh * 2 + 0] + __ldg(bias + col);
                    float z1 = acc[0][mf][nf][rh * 2 + 1] + __ldg(bias + col + 1);
                    float a0 = acc[1][mf][nf][rh * 2 + 0], a1 = acc[1][mf][nf][rh * 2 + 1];
                    float c0 = acc[2][mf][nf][rh * 2 + 0], c1 = acc[2][mf][nf][rh * 2 + 1];
                    float h0 = my_tanh(z0), h1 = my_tanh(z1);
                    float g0 = fmaf(-h0, h0, 1.0f), g1 = fmaf(-h1, h1, 1.0f);
                    float e0 = g0 * fmaf(-2.0f * h0 * a0, a0, c0);
                    float e1 = g1 * fmaf(-2.0f * h1 * a1, a1, c1);
                    float w30 = __ldg(W3 + col), w31 = __ldg(W3 + col + 1);
                    su[mf][rh] = fmaf(h0, w30, fmaf(h1, w31, su[mf][rh]));
                    se[mf][rh] = fmaf(e0, w30, fmaf(e1, w31, se[mf][rh]));
                }
#pragma unroll
        for (int mf = 0; mf < 2; mf++)
#pragma unroll
            for (int rh = 0; rh < 2; rh++) {
                float s = su[mf][rh];
                s += __shfl_xor_sync(0xffffffffu, s, 1);
                s += __shfl_xor_sync(0xffffffffu, s, 2);
                float t = se[mf][rh];
                t += __shfl_xor_sync(0xffffffffu, t, 1);
                t += __shfl_xor_sync(0xffffffffu, t, 2);
                if (lq == 0) {
                    const int row = m0 + wm * 32 + mf * 16 + rh * 8 + lg;
                    const int p = nt * 2 + wn;
                    g_part[(size_t)row * 16 + p]     = s;
                    g_part[(size_t)row * 16 + 8 + p] = t;
                }
            }
    }
}

// ---------------- tiny kernels ----------------
__global__ void k_head(const float* __restrict__ x, const float* __restrict__ wts,
                       const float* __restrict__ b3) {
    int i = blockIdx.x * 256 + threadIdx.x;
    const float* p = g_part + (size_t)i * 16;
    float4 a0 = *(const float4*)p,       a1 = *(const float4*)(p + 4);
    float4 a2 = *(const float4*)(p + 8), a3 = *(const float4*)(p + 12);
    float su = ((a0.x + a0.y) + (a0.z + a0.w)) + ((a1.x + a1.y) + (a1.z + a1.w));
    float se = ((a2.x + a2.y) + (a2.z + a2.w)) + ((a3.x + a3.y) + (a3.z + a3.w));
    float xi = x[i];
    g_r[i] = wts[i] * (se + my_sin(PI_F * xi));
    if (i == 0)         g_ub[0] = su + __ldg(b3);
    if (i == N_PTS - 1) g_ub[1] = su + __ldg(b3);
}

// Spectral partials: grid = 128 k-groups x 8 point-segments.
__global__ __launch_bounds__(256) void k_spec(const float* __restrict__ x) {
    const int kg  = blockIdx.x >> 3;
    const int seg = blockIdx.x & 7;
    const int k0  = kg * 8;
    const int i0  = seg * 4096;
    float pk[8];
#pragma unroll
    for (int q = 0; q < 8; q++) pk[q] = PI_F * (float)(k0 + 1 + q);
    float acc[8] = {0, 0, 0, 0, 0, 0, 0, 0};
    for (int i = threadIdx.x; i < 4096; i += 256) {
        float xi = x[i0 + i], ri = g_r[i0 + i];
#pragma unroll
        for (int q = 0; q < 8; q++)
            acc[q] = fmaf(my_sin(pk[q] * xi), ri, acc[q]);
    }
    __shared__ float sred[8][8];
    int lane = threadIdx.x & 31, wid = threadIdx.x >> 5;
#pragma unroll
    for (int q = 0; q < 8; q++) {
        float v = acc[q];
#pragma unroll
        for (int o = 16; o; o >>= 1) v += __shfl_down_sync(0xffffffffu, v, o);
        if (lane == 0) sred[q][wid] = v;
    }
    __syncthreads();
    if (threadIdx.x < 8) {
        float s = 0.f;
#pragma unroll
        for (int w = 0; w < 8; w++) s += sred[threadIdx.x][w];
        g_Sp[seg * KTEST + k0 + threadIdx.x] = s;
    }
}

__global__ void k_final(float* __restrict__ out) {
    __shared__ float sred[8];
    float s = 0.f;
    for (int t = threadIdx.x; t < KTEST; t += 256) {
        float v = 0.f;
#pragma unroll
        for (int seg = 0; seg < 8; seg++) v += g_Sp[seg * KTEST + t];
        s = fmaf(v, v, s);
    }
    int lane = threadIdx.x & 31, wid = threadIdx.x >> 5;
#pragma unroll
    for (int o = 16; o; o >>= 1) s += __shfl_down_sync(0xffffffffu, s, o);
    if (lane == 0) sred[wid] = s;
    __syncthreads();
    if (threadIdx.x == 0) {
        float t = 0.f;
#pragma unroll
        for (int w = 0; w < 8; w++) t += sred[w];
        out[0] = t * (1.0f / 1024.0f);
        out[1] = 5.0f * (g_ub[0] * g_ub[0] + g_ub[1] * g_ub[1]);
    }
}

extern "C" void kernel_launch(void* const* d_in, const int* in_sizes, int n_in,
                              void* d_out, int out_size) {
    const float* x   = (const float*)d_in[0];
    const float* wts = (const float*)d_in[1];
    const float* W0  = (const float*)d_in[2];
    const float* b0  = (const float*)d_in[3];
    const float* W1  = (const float*)d_in[4];
    const float* b1  = (const float*)d_in[5];
    const float* W2  = (const float*)d_in[6];
    const float* b2  = (const float*)d_in[7];
    const float* W3  = (const float*)d_in[8];
    const float* b3  = (const float*)d_in[9];

    void *pA = nullptr, *pB = nullptr;
    cudaGetSymbolAddress(&pA, g_jetA);
    cudaGetSymbolAddress(&pB, g_jetB);
    __nv_bfloat16* jA = (__nv_bfloat16*)pA;
    __nv_bfloat16* jB = (__nv_bfloat16*)pB;

    cudaFuncSetAttribute(k_layer<1>, cudaFuncAttributeMaxDynamicSharedMemorySize, SMEM2);
    cudaFuncSetAttribute(k_layer<0>, cudaFuncAttributeMaxDynamicSharedMemorySize, SMEM2);

    k_init    <<<N_PTS * 128 / 256, 256>>>(x, W0, b0);
    k_layer<1><<<1024, 256, SMEM2>>>(jA, jB, W1, b1, nullptr);
    k_layer<0><<<1024, 256, SMEM2>>>(jB, nullptr, W2, b2, W3);
    k_head    <<<N_PTS / 256, 256>>>(x, wts, b3);
    k_spec    <<<KTEST, 256>>>(x);
    k_final   <<<1, 256>>>((float*)d_out);
}

// round 7
// speedup vs baseline: 1.7781x; 1.0010x over previous
#include <cuda_runtime.h>
#include <cuda_bf16.h>
#include <cstdint>
#include <cstddef>

#define N_PTS 32768
#define HID   256
#define KTEST 1024
#define PI_F  3.14159274101257324f

// ---------------- global scratch ----------------
// Jet buffers, pre-split bf16: index ((m*3 + ch)*2 + hl)*256 + k
__device__ __nv_bfloat16 g_jetA[(size_t)N_PTS * 3 * 2 * HID];
__device__ __nv_bfloat16 g_jetB[(size_t)N_PTS * 3 * 2 * HID];
__device__ float g_part[(size_t)N_PTS * 16];   // [row][ch(2)][8 partials]
__device__ float g_r[N_PTS];
__device__ float g_Sp[8 * KTEST];              // [seg][k] spectral partials
__device__ float g_ub[2];

// ---------------- math helpers (flag-independent) ----------------
__device__ __forceinline__ float frcp(float x) {
    float r;
    asm("rcp.approx.f32 %0, %1;" : "=f"(r) : "f"(x));
    return r;
}

// 4 tanh with ONE reciprocal (batch-inverse): 4x EX2 + 1x RCP = 1.25 MUFU/tanh.
// Overflow-safe: |z| clamped to 9 -> e^{2z} <= 6.6e7, 4-product <= 1.9e31.
__device__ __forceinline__ void tanh4(const float* z, float* h) {
    float e[4], ep[4];
#pragma unroll
    for (int i = 0; i < 4; i++) {
        float zc = fminf(fmaxf(z[i], -9.0f), 9.0f);
        e[i]  = __expf(2.0f * zc);
        ep[i] = e[i] + 1.0f;
    }
    float p01   = ep[0] * ep[1];
    float p012  = p01 * ep[2];
    float p0123 = p012 * ep[3];
    float r = frcp(p0123);
    float i3 = p012 * r;  r *= ep[3];
    float i2 = p01  * r;  r *= ep[2];
    float i1 = ep[0] * r; r *= ep[1];
    float i0 = r;
    h[0] = (e[0] - 1.0f) * i0;
    h[1] = (e[1] - 1.0f) * i1;
    h[2] = (e[2] - 1.0f) * i2;
    h[3] = (e[3] - 1.0f) * i3;
}

__device__ __forceinline__ float my_sin(float a) {
    const float INV_PI = 0.3183098861837907f;
    float n = rintf(a * INV_PI);
    float r = fmaf(n, -3.14159274101257324f, a);
    r = fmaf(n, 8.742277657347586e-8f, r);
    float s2 = r * r;
    float p = -2.50521084e-8f;
    p = fmaf(p, s2, 2.75573192e-6f);
    p = fmaf(p, s2, -1.98412698e-4f);
    p = fmaf(p, s2, 8.33333333e-3f);
    p = fmaf(p, s2, -1.66666667e-1f);
    float s = fmaf(p * s2, r, r);
    return (((int)n) & 1) ? -s : s;
}

__device__ __forceinline__ void bsplit(float v, __nv_bfloat16& hi, __nv_bfloat16& lo) {
    hi = __float2bfloat16(v);
    lo = __float2bfloat16(v - __bfloat162float(hi));
}

// bf16 HMMA (sm_80+ PTX — valid on plain sm_103 target).
__device__ __forceinline__ void mma16816(float* d, const uint32_t* a, const uint32_t* b) {
    asm volatile(
        "mma.sync.aligned.m16n8k16.row.col.f32.bf16.bf16.f32 "
        "{%0,%1,%2,%3}, {%4,%5,%6,%7}, {%8,%9}, {%0,%1,%2,%3};"
        : "+f"(d[0]), "+f"(d[1]), "+f"(d[2]), "+f"(d[3])
        : "r"(a[0]), "r"(a[1]), "r"(a[2]), "r"(a[3]), "r"(b[0]), "r"(b[1]));
}

__device__ __forceinline__ uint32_t smem_u32(const void* p) {
    uint32_t a;
    asm("{ .reg .u64 t; cvta.to.shared.u64 t, %1; cvt.u32.u64 %0, t; }" : "=r"(a) : "l"(p));
    return a;
}

// ---------------- SMEM geometry (bf16 elements) ----------------
#define SB_E    264                  // B k-stride (256 + 8 pad) -> conflict-free
#define BHI_E   0
#define BLO_E   16896                // 64 * 264
#define AB_E    33792                // A region start
#define SA2     40                   // A k-stride (K=32 chunk + pad)
#define TILE2_E (128 * SA2)          // 5120
#define ABUF_E  (6 * TILE2_E)        // 30720 (one double-buffer half)
#define SMEM2   ((AB_E + 12 * TILE2_E) * 2)   // 190464 B

// ---------------- MMA compute for one K=32 chunk ----------------
__device__ __forceinline__ void compute_chunk(
    const __nv_bfloat16* sm, int aBase, int bK0,
    int wm, int wn, int lg, int lq, float acc[3][2][4][4])
{
#pragma unroll
    for (int ks = 0; ks < 2; ks++) {
        const int ka = ks * 16 + lq * 2;
        const int kb = bK0 + ka;
        uint32_t bh[4][2], bl[4][2];
#pragma unroll
        for (int nf = 0; nf < 4; nf++) {
            const __nv_bfloat16* p = sm + (wn * 32 + nf * 8 + lg) * SB_E + kb;
            bh[nf][0] = *(const uint32_t*)p;
            bh[nf][1] = *(const uint32_t*)(p + 8);
            bl[nf][0] = *(const uint32_t*)(p + BLO_E);
            bl[nf][1] = *(const uint32_t*)(p + BLO_E + 8);
        }
#pragma unroll
        for (int ch = 0; ch < 3; ch++) {
            uint32_t ah[2][4], al[2][4];
#pragma unroll
            for (int mf = 0; mf < 2; mf++) {
                const __nv_bfloat16* p = sm + aBase + (ch * 2) * TILE2_E
                                       + (wm * 32 + mf * 16 + lg) * SA2 + ka;
                ah[mf][0] = *(const uint32_t*)p;
                ah[mf][1] = *(const uint32_t*)(p + 8 * SA2);
                ah[mf][2] = *(const uint32_t*)(p + 8);
                ah[mf][3] = *(const uint32_t*)(p + 8 * SA2 + 8);
                const __nv_bfloat16* q = p + TILE2_E;
                al[mf][0] = *(const uint32_t*)q;
                al[mf][1] = *(const uint32_t*)(q + 8 * SA2);
                al[mf][2] = *(const uint32_t*)(q + 8);
                al[mf][3] = *(const uint32_t*)(q + 8 * SA2 + 8);
            }
#pragma unroll
            for (int mf = 0; mf < 2; mf++)
#pragma unroll
                for (int nf = 0; nf < 4; nf++) {
                    mma16816(acc[ch][mf][nf], ah[mf], bh[nf]);  // hi*hi
                    mma16816(acc[ch][mf][nf], ah[mf], bl[nf]);  // hi*lo
                    mma16816(acc[ch][mf][nf], al[mf], bh[nf]);  // lo*hi
                }
        }
    }
}

// cp.async prefetch of one K=32 A-chunk from a jet buffer.
__device__ __forceinline__ void issue_chunk(uint32_t smA_byte, const __nv_bfloat16* jin,
                                            int m0, int c, int tid) {
    const int kc = c * 32;
    const uint32_t dbase = smA_byte + (uint32_t)((c & 1) * ABUF_E) * 2;
#pragma unroll
    for (int it = 0; it < 12; it++) {
        int seg = tid + it * 256;
        int t = seg >> 9, rem = seg & 511;
        int r = rem >> 2, s4 = rem & 3;
        const __nv_bfloat16* src = jin
            + (((size_t)((m0 + r) * 3 + (t >> 1)) * 2 + (t & 1)) << 8) + kc + s4 * 8;
        uint32_t dst = dbase + (uint32_t)(t * TILE2_E + r * SA2 + s4 * 8) * 2;
        unsigned long long gsrc = (unsigned long long)__cvta_generic_to_global(src);
        asm volatile("cp.async.cg.shared.global [%0], [%1], 16;" :: "r"(dst), "l"(gsrc) : "memory");
    }
    asm volatile("cp.async.commit_group;" ::: "memory");
}

// ---------------- layer-0 jet init (split bf16), 4 k-values/thread ----------------
__global__ __launch_bounds__(256) void k_init(const float* __restrict__ x,
                                              const float* __restrict__ W0,
                                              const float* __restrict__ b0) {
    int gid = blockIdx.x * 256 + threadIdx.x;
    int m  = gid >> 6;
    int k  = (gid & 63) << 2;
    float xm = __ldg(x + m);
    float z[4], w[4], h[4];
#pragma unroll
    for (int u = 0; u < 4; u++) {
        w[u] = __ldg(W0 + k + u);
        z[u] = fmaf(xm, w[u], __ldg(b0 + k + u));
    }
    tanh4(z, h);
    __nv_bfloat16 st[3][2][4];
#pragma unroll
    for (int u = 0; u < 4; u++) {
        float g  = fmaf(-h[u], h[u], 1.0f);
        float d  = g * w[u];
        float e2 = -2.0f * h[u] * g * w[u] * w[u];
        bsplit(h[u], st[0][0][u], st[0][1][u]);
        bsplit(d,    st[1][0][u], st[1][1][u]);
        bsplit(e2,   st[2][0][u], st[2][1][u]);
    }
#pragma unroll
    for (int ch = 0; ch < 3; ch++)
#pragma unroll
        for (int hl = 0; hl < 2; hl++)
            *(uint2*)(g_jetA + (((size_t)(m * 3 + ch) * 2 + hl) << 8) + k)
                = *(uint2*)st[ch][hl];
}

// ---------------- fused hidden layer ----------------
// WRITE_JET=1: epilogue writes split-bf16 jets to jout (layer 1).
// WRITE_JET=0: epilogue writes head partial dots to g_part (layer 2).
template<int WRITE_JET>
__global__ __launch_bounds__(256) void k_layer(
    const __nv_bfloat16* __restrict__ jin, __nv_bfloat16* __restrict__ jout,
    const float* __restrict__ W, const float* __restrict__ bias,
    const float* __restrict__ W3)
{
    extern __shared__ __nv_bfloat16 sm[];
    const int tid = threadIdx.x, lane = tid & 31, wid = tid >> 5;
    const int wm = wid & 3, wn = wid >> 2;
    const int lg = lane >> 2, lq = lane & 3;
    const int nt = blockIdx.x & 3, mt = blockIdx.x >> 2;
    const int m0 = mt * 128, n0 = nt * 64;

    const uint32_t smA = smem_u32(sm) + AB_E * 2;
    issue_chunk(smA, jin, m0, 0, tid);
    issue_chunk(smA, jin, m0, 1, tid);

    // ---- stage B (full K=256): W[k][n] -> Bhi/Blo [n][k] ----
#pragma unroll
    for (int it = 0; it < 16; it++) {
        int e = tid + it * 256;
        int k = e >> 4, n4 = e & 15;
        float4 v = *(const float4*)(W + (size_t)k * HID + n0 + n4 * 4);
        float vv[4] = {v.x, v.y, v.z, v.w};
#pragma unroll
        for (int u = 0; u < 4; u++) {
            __nv_bfloat16 hh, ll; bsplit(vv[u], hh, ll);
            int off = (n4 * 4 + u) * SB_E + k;
            sm[BHI_E + off] = hh;
            sm[BLO_E + off] = ll;
        }
    }

    float acc[3][2][4][4];
#pragma unroll
    for (int ch = 0; ch < 3; ch++)
#pragma unroll
        for (int mf = 0; mf < 2; mf++)
#pragma unroll
            for (int nf = 0; nf < 4; nf++)
#pragma unroll
                for (int rr = 0; rr < 4; rr++) acc[ch][mf][nf][rr] = 0.f;

    // ---- 8 chunks of K=32, cp.async double-buffered ----
    for (int c = 0; c < 8; c++) {
        if (c < 7) { asm volatile("cp.async.wait_group 1;" ::: "memory"); }
        else       { asm volatile("cp.async.wait_group 0;" ::: "memory"); }
        __syncthreads();
        compute_chunk(sm, AB_E + (c & 1) * ABUF_E, c * 32, wm, wn, lg, lq, acc);
        __syncthreads();
        if (c + 2 < 8) issue_chunk(smA, jin, m0, c + 2, tid);
    }

    // ---- epilogue (batched tanh: 8 per (mf,rh) group, 2x tanh4) ----
    if (WRITE_JET) {
#pragma unroll
        for (int mf = 0; mf < 2; mf++)
#pragma unroll
            for (int rh = 0; rh < 2; rh++) {
                const int row = m0 + wm * 32 + mf * 16 + rh * 8 + lg;
                float zz[8], aa[8], cc[8], hh[8];
#pragma unroll
                for (int nf = 0; nf < 4; nf++)
#pragma unroll
                    for (int u = 0; u < 2; u++) {
                        const int e = nf * 2 + u;
                        const int col = n0 + wn * 32 + nf * 8 + lq * 2 + u;
                        zz[e] = acc[0][mf][nf][rh * 2 + u] + __ldg(bias + col);
                        aa[e] = acc[1][mf][nf][rh * 2 + u];
                        cc[e] = acc[2][mf][nf][rh * 2 + u];
                    }
                tanh4(zz, hh);
                tanh4(zz + 4, hh + 4);
#pragma unroll
                for (int nf = 0; nf < 4; nf++) {
                    const int col = n0 + wn * 32 + nf * 8 + lq * 2;
                    const int e0 = nf * 2, e1 = nf * 2 + 1;
                    float h0 = hh[e0], h1 = hh[e1];
                    float g0 = fmaf(-h0, h0, 1.0f), g1 = fmaf(-h1, h1, 1.0f);
                    float d0 = g0 * aa[e0], d1 = g1 * aa[e1];
                    float ev0 = g0 * fmaf(-2.0f * h0 * aa[e0], aa[e0], cc[e0]);
                    float ev1 = g1 * fmaf(-2.0f * h1 * aa[e1], aa[e1], cc[e1]);
                    float vs[3][2] = {{h0, h1}, {d0, d1}, {ev0, ev1}};
#pragma unroll
                    for (int ch = 0; ch < 3; ch++) {
                        __nv_bfloat16 hA, lA, hB, lB;
                        bsplit(vs[ch][0], hA, lA);
                        bsplit(vs[ch][1], hB, lB);
                        __nv_bfloat162 hp = __halves2bfloat162(hA, hB);
                        __nv_bfloat162 lp = __halves2bfloat162(lA, lB);
                        *(uint32_t*)(jout + (((size_t)(row * 3 + ch) * 2 + 0) << 8) + col) = *(uint32_t*)&hp;
                        *(uint32_t*)(jout + (((size_t)(row * 3 + ch) * 2 + 1) << 8) + col) = *(uint32_t*)&lp;
                    }
                }
            }
    } else {
        float su[2][2] = {{0.f, 0.f}, {0.f, 0.f}};
        float se[2][2] = {{0.f, 0.f}, {0.f, 0.f}};
#pragma unroll
        for (int mf = 0; mf < 2; mf++)
#pragma unroll
            for (int rh = 0; rh < 2; rh++) {
                float zz[8], aa[8], cc[8], hh[8];
#pragma unroll
                for (int nf = 0; nf < 4; nf++)
#pragma unroll
                    for (int u = 0; u < 2; u++) {
                        const int e = nf * 2 + u;
                        const int col = n0 + wn * 32 + nf * 8 + lq * 2 + u;
                        zz[e] = acc[0][mf][nf][rh * 2 + u] + __ldg(bias + col);
                        aa[e] = acc[1][mf][nf][rh * 2 + u];
                        cc[e] = acc[2][mf][nf][rh * 2 + u];
                    }
                tanh4(zz, hh);
                tanh4(zz + 4, hh + 4);
#pragma unroll
                for (int nf = 0; nf < 4; nf++) {
                    const int col = n0 + wn * 32 + nf * 8 + lq * 2;
                    const int e0 = nf * 2, e1 = nf * 2 + 1;
                    float h0 = hh[e0], h1 = hh[e1];
                    float g0 = fmaf(-h0, h0, 1.0f), g1 = fmaf(-h1, h1, 1.0f);
                    float ev0 = g0 * fmaf(-2.0f * h0 * aa[e0], aa[e0], cc[e0]);
                    float ev1 = g1 * fmaf(-2.0f * h1 * aa[e1], aa[e1], cc[e1]);
                    float w30 = __ldg(W3 + col), w31 = __ldg(W3 + col + 1);
                    su[mf][rh] = fmaf(h0, w30, fmaf(h1, w31, su[mf][rh]));
                    se[mf][rh] = fmaf(ev0, w30, fmaf(ev1, w31, se[mf][rh]));
                }
            }
#pragma unroll
        for (int mf = 0; mf < 2; mf++)
#pragma unroll
            for (int rh = 0; rh < 2; rh++) {
                float s = su[mf][rh];
                s += __shfl_xor_sync(0xffffffffu, s, 1);
                s += __shfl_xor_sync(0xffffffffu, s, 2);
                float t = se[mf][rh];
                t += __shfl_xor_sync(0xffffffffu, t, 1);
                t += __shfl_xor_sync(0xffffffffu, t, 2);
                if (lq == 0) {
                    const int row = m0 + wm * 32 + mf * 16 + rh * 8 + lg;
                    const int p = nt * 2 + wn;
                    g_part[(size_t)row * 16 + p]     = s;
                    g_part[(size_t)row * 16 + 8 + p] = t;
                }
            }
    }
}

// ---------------- tiny kernels ----------------
__global__ void k_head(const float* __restrict__ x, const float* __restrict__ wts,
                       const float* __restrict__ b3) {
    int i = blockIdx.x * 256 + threadIdx.x;
    const float* p = g_part + (size_t)i * 16;
    float4 a0 = *(const float4*)p,       a1 = *(const float4*)(p + 4);
    float4 a2 = *(const float4*)(p + 8), a3 = *(const float4*)(p + 12);
    float su = ((a0.x + a0.y) + (a0.z + a0.w)) + ((a1.x + a1.y) + (a1.z + a1.w));
    float se = ((a2.x + a2.y) + (a2.z + a2.w)) + ((a3.x + a3.y) + (a3.z + a3.w));
    float xi = x[i];
    g_r[i] = wts[i] * (se + my_sin(PI_F * xi));
    if (i == 0)         g_ub[0] = su + __ldg(b3);
    if (i == N_PTS - 1) g_ub[1] = su + __ldg(b3);
}

// Spectral partials: grid = 128 k-groups x 8 point-segments.
__global__ __launch_bounds__(256) void k_spec(const float* __restrict__ x) {
    const int kg  = blockIdx.x >> 3;
    const int seg = blockIdx.x & 7;
    const int k0  = kg * 8;
    const int i0  = seg * 4096;
    float pk[8];
#pragma unroll
    for (int q = 0; q < 8; q++) pk[q] = PI_F * (float)(k0 + 1 + q);
    float acc[8] = {0, 0, 0, 0, 0, 0, 0, 0};
    for (int i = threadIdx.x; i < 4096; i += 256) {
        float xi = x[i0 + i], ri = g_r[i0 + i];
#pragma unroll
        for (int q = 0; q < 8; q++)
            acc[q] = fmaf(my_sin(pk[q] * xi), ri, acc[q]);
    }
    __shared__ float sred[8][8];
    int lane = threadIdx.x & 31, wid = threadIdx.x >> 5;
#pragma unroll
    for (int q = 0; q < 8; q++) {
        float v = acc[q];
#pragma unroll
        for (int o = 16; o; o >>= 1) v += __shfl_down_sync(0xffffffffu, v, o);
        if (lane == 0) sred[q][wid] = v;
    }
    __syncthreads();
    if (threadIdx.x < 8) {
        float s = 0.f;
#pragma unroll
        for (int w = 0; w < 8; w++) s += sred[threadIdx.x][w];
        g_Sp[seg * KTEST + k0 + threadIdx.x] = s;
    }
}

__global__ void k_final(float* __restrict__ out) {
    __shared__ float sred[8];
    float s = 0.f;
    for (int t = threadIdx.x; t < KTEST; t += 256) {
        float v = 0.f;
#pragma unroll
        for (int seg = 0; seg < 8; seg++) v += g_Sp[seg * KTEST + t];
        s = fmaf(v, v, s);
    }
    int lane = threadIdx.x & 31, wid = threadIdx.x >> 5;
#pragma unroll
    for (int o = 16; o; o >>= 1) s += __shfl_down_sync(0xffffffffu, s, o);
    if (lane == 0) sred[wid] = s;
    __syncthreads();
    if (threadIdx.x == 0) {
        float t = 0.f;
#pragma unroll
        for (int w = 0; w < 8; w++) t += sred[w];
        out[0] = t * (1.0f / 1024.0f);
        out[1] = 5.0f * (g_ub[0] * g_ub[0] + g_ub[1] * g_ub[1]);
    }
}

extern "C" void kernel_launch(void* const* d_in, const int* in_sizes, int n_in,
                              void* d_out, int out_size) {
    const float* x   = (const float*)d_in[0];
    const float* wts = (const float*)d_in[1];
    const float* W0  = (const float*)d_in[2];
    const float* b0  = (const float*)d_in[3];
    const float* W1  = (const float*)d_in[4];
    const float* b1  = (const float*)d_in[5];
    const float* W2  = (const float*)d_in[6];
    const float* b2  = (const float*)d_in[7];
    const float* W3  = (const float*)d_in[8];
    const float* b3  = (const float*)d_in[9];

    void *pA = nullptr, *pB = nullptr;
    cudaGetSymbolAddress(&pA, g_jetA);
    cudaGetSymbolAddress(&pB, g_jetB);
    __nv_bfloat16* jA = (__nv_bfloat16*)pA;
    __nv_bfloat16* jB = (__nv_bfloat16*)pB;

    cudaFuncSetAttribute(k_layer<1>, cudaFuncAttributeMaxDynamicSharedMemorySize, SMEM2);
    cudaFuncSetAttribute(k_layer<0>, cudaFuncAttributeMaxDynamicSharedMemorySize, SMEM2);

    k_init    <<<N_PTS * 64 / 256, 256>>>(x, W0, b0);
    k_layer<1><<<1024, 256, SMEM2>>>(jA, jB, W1, b1, nullptr);
    k_layer<0><<<1024, 256, SMEM2>>>(jB, nullptr, W2, b2, W3);
    k_head    <<<N_PTS / 256, 256>>>(x, wts, b3);
    k_spec    <<<KTEST, 256>>>(x);
    k_final   <<<1, 256>>>((float*)d_out);
}